// round 2
// baseline (speedup 1.0000x reference)
#include <cuda_runtime.h>
#include <math.h>

#define S   129
#define SV  (S*S*S)
#define L   224
#define L2  (L*L)
#define LV  (L*L*L)
#define OFF 48           // L/2 - S/2
#define CABS 0.2f

// Scratch (allocation-free rule: __device__ globals)
__device__ float g_up0[LV];          // transmittance volume, light 0 (45 MB)
__device__ float g_up1[LV];          // transmittance volume, light 1 (45 MB)
__device__ float g_comb[3 * SV];     // combined 3-channel light field (26 MB)

struct Mat3 { float m[9]; };

// ---------- trilinear samplers ----------

__device__ __forceinline__ float fetchS(const float* __restrict__ v, int z, int y, int x) {
    if ((unsigned)x < (unsigned)S && (unsigned)y < (unsigned)S && (unsigned)z < (unsigned)S)
        return __ldg(v + ((size_t)z * S + y) * S + x);
    return 0.f;
}

// Sample the 129^3 density with zero padding; cheap full-OOB reject.
__device__ __forceinline__ float triS(const float* __restrict__ v, float x, float y, float z) {
    if (x <= -1.f || x >= (float)S || y <= -1.f || y >= (float)S || z <= -1.f || z >= (float)S)
        return 0.f;
    float fx = floorf(x), fy = floorf(y), fz = floorf(z);
    int x0 = (int)fx, y0 = (int)fy, z0 = (int)fz;
    float wx = x - fx, wy = y - fy, wz = z - fz;
    float c000 = fetchS(v, z0,     y0,     x0);
    float c001 = fetchS(v, z0,     y0,     x0 + 1);
    float c010 = fetchS(v, z0,     y0 + 1, x0);
    float c011 = fetchS(v, z0,     y0 + 1, x0 + 1);
    float c100 = fetchS(v, z0 + 1, y0,     x0);
    float c101 = fetchS(v, z0 + 1, y0,     x0 + 1);
    float c110 = fetchS(v, z0 + 1, y0 + 1, x0);
    float c111 = fetchS(v, z0 + 1, y0 + 1, x0 + 1);
    float c00 = c000 + wx * (c001 - c000);
    float c01 = c010 + wx * (c011 - c010);
    float c10 = c100 + wx * (c101 - c100);
    float c11 = c110 + wx * (c111 - c110);
    float c0  = c00 + wy * (c01 - c00);
    float c1  = c10 + wy * (c11 - c10);
    return c0 + wz * (c1 - c0);
}

__device__ __forceinline__ float fetchL(const float* __restrict__ v, int z, int y, int x) {
    if ((unsigned)x < (unsigned)L && (unsigned)y < (unsigned)L && (unsigned)z < (unsigned)L)
        return __ldg(v + ((size_t)z * L + y) * L + x);
    return 0.f;
}

// Sample the 224^3 transmittance volume (samples provably interior; mask is safety).
__device__ __forceinline__ float triL(const float* __restrict__ v, float x, float y, float z) {
    float fx = floorf(x), fy = floorf(y), fz = floorf(z);
    int x0 = (int)fx, y0 = (int)fy, z0 = (int)fz;
    float wx = x - fx, wy = y - fy, wz = z - fz;
    float c000 = fetchL(v, z0,     y0,     x0);
    float c001 = fetchL(v, z0,     y0,     x0 + 1);
    float c010 = fetchL(v, z0,     y0 + 1, x0);
    float c011 = fetchL(v, z0,     y0 + 1, x0 + 1);
    float c100 = fetchL(v, z0 + 1, y0,     x0);
    float c101 = fetchL(v, z0 + 1, y0,     x0 + 1);
    float c110 = fetchL(v, z0 + 1, y0 + 1, x0);
    float c111 = fetchL(v, z0 + 1, y0 + 1, x0 + 1);
    float c00 = c000 + wx * (c001 - c000);
    float c01 = c010 + wx * (c011 - c010);
    float c10 = c100 + wx * (c101 - c100);
    float c11 = c110 + wx * (c111 - c110);
    float c0  = c00 + wy * (c01 - c00);
    float c1  = c10 + wy * (c11 - c10);
    return c0 + wz * (c1 - c0);
}

// ---------- kernel A: rotate + suffix-cumsum + exp ----------
// One thread per (y,x) column; blockIdx.y selects the light (both in one launch
// to double resident parallelism — kA is latency-bound on the gather chain).
// up[z,y,x] = exp(-c * sum_{z'>=z} rot(d)[z',y,x])
__global__ void __launch_bounds__(128) kA(const float* __restrict__ d, Mat3 R0, Mat3 R1) {
    int t = blockIdx.x * blockDim.x + threadIdx.x;
    if (t >= L2) return;
    int which = blockIdx.y;
    const Mat3& R = which ? R1 : R0;
    float* __restrict__ up = which ? g_up1 : g_up0;
    int x = t % L, y = t / L;
    float bx = -1.f + 2.f * (float)x / 223.f;
    float by = -1.f + 2.f * (float)y / 223.f;
    // sample_k(z) = 111.5*(R[k,0]bx + R[k,1]by + 1 - R[k,2]) + z*R[k,2]  (then -OFF into d-space)
    float A0 = 111.5f * (R.m[0] * bx + R.m[1] * by + 1.f - R.m[2]) - (float)OFF;
    float A1 = 111.5f * (R.m[3] * bx + R.m[4] * by + 1.f - R.m[5]) - (float)OFF;
    float A2 = 111.5f * (R.m[6] * bx + R.m[7] * by + 1.f - R.m[8]) - (float)OFF;
    float s = 0.f;
    #pragma unroll 2
    for (int z = L - 1; z >= 0; --z) {
        float zf = (float)z;
        float px = fmaf(zf, R.m[2], A0);
        float py = fmaf(zf, R.m[5], A1);
        float pz = fmaf(zf, R.m[8], A2);
        s += triS(d, px, py, pz);
        up[(size_t)z * L2 + t] = expf(-CABS * s);
    }
}

// ---------- kernel B: back-rotate both lights, write 3-channel combined field ----------
__global__ void __launch_bounds__(256) kB(Mat3 R0, Mat3 R1) {
    int v = blockIdx.x * blockDim.x + threadIdx.x;
    if (v >= SV) return;
    int x = v % S;
    int y = (v / S) % S;
    int z = v / (S * S);
    float bx = -1.f + 2.f * (float)(x + OFF) / 223.f;
    float by = -1.f + 2.f * (float)(y + OFF) / 223.f;
    float bz = -1.f + 2.f * (float)(z + OFF) / 223.f;
    // back matrix = R^T: src_k = sum_c R[c,k]*b_c
    float s0 = triL(g_up0,
        111.5f * (R0.m[0] * bx + R0.m[3] * by + R0.m[6] * bz + 1.f),
        111.5f * (R0.m[1] * bx + R0.m[4] * by + R0.m[7] * bz + 1.f),
        111.5f * (R0.m[2] * bx + R0.m[5] * by + R0.m[8] * bz + 1.f));
    float s1 = triL(g_up1,
        111.5f * (R1.m[0] * bx + R1.m[3] * by + R1.m[6] * bz + 1.f),
        111.5f * (R1.m[1] * bx + R1.m[4] * by + R1.m[7] * bz + 1.f),
        111.5f * (R1.m[2] * bx + R1.m[5] * by + R1.m[8] * bz + 1.f));
    // rgb0 = (1, 69/255, 25/255), rgb1 = (227/255, 1, 66/255)
    g_comb[v]            = s0 * 1.0f               + s1 * (227.f / 255.f);
    g_comb[SV + v]       = s0 * (69.f / 255.f)     + s1 * 1.0f;
    g_comb[2 * SV + v]   = s0 * (25.f / 255.f)     + s1 * (66.f / 255.f);
}

// ---------- kernel C: view-ray compositing ----------
__global__ void __launch_bounds__(128) kC(const float* __restrict__ d, float* __restrict__ out) {
    int t = blockIdx.x * blockDim.x + threadIdx.x;
    if (t >= S * S) return;
    float ts = 0.f, a0 = 0.f, a1 = 0.f, a2 = 0.f;
    #pragma unroll 2
    for (int z = S - 1; z >= 0; --z) {
        size_t idx = (size_t)z * S * S + t;
        float dv = __ldg(d + idx);
        ts += dv;
        float tr = expf(-CABS * ts);
        float w = dv * tr;
        a0 = fmaf(w, g_comb[idx],           a0);
        a1 = fmaf(w, g_comb[SV + idx],      a1);
        a2 = fmaf(w, g_comb[2 * SV + idx],  a2);
    }
    out[t]             = fminf(fmaxf(CABS * a0, 0.f), 1.f);
    out[S * S + t]     = fminf(fmaxf(CABS * a1, 0.f), 1.f);
    out[2 * S * S + t] = fminf(fmaxf(CABS * a2, 0.f), 1.f);
}

// ---------- host ----------

static void light_matrix(double lx, double ly, double lz, Mat3* Rf) {
    double n = sqrt(lx * lx + ly * ly + lz * lz);
    double ldx = lx / n, ldy = ly / n, ldz = lz / n;
    double yw = -asin(ldx);
    if (ldz < 0) yw = -M_PI - yw;
    double p = asin(ldy);
    double cy = cos(yw), sy = sin(yw), cp = cos(p), sp = sin(p);
    // R = Ry @ Rp
    double R[9] = { cy,  sy * sp,  sy * cp,
                    0.0, cp,      -sp,
                   -sy,  cy * sp,  cy * cp };
    for (int i = 0; i < 9; i++) Rf->m[i] = (float)R[i];
}

extern "C" void kernel_launch(void* const* d_in, const int* in_sizes, int n_in,
                              void* d_out, int out_size) {
    const float* d = (const float*)d_in[0];
    float* out = (float*)d_out;

    Mat3 R0, R1;
    light_matrix(2.0, 1.0, 1.0, &R0);
    light_matrix(-1.0, 0.5, 0.0, &R1);

    dim3 gridA((L2 + 127) / 128, 2, 1);
    kA<<<gridA, 128>>>(d, R0, R1);
    kB<<<(SV + 255) / 256, 256>>>(R0, R1);
    kC<<<(S * S + 127) / 128, 128>>>(d, out);
}

// round 3
// speedup vs baseline: 1.6661x; 1.6661x over previous
#include <cuda_runtime.h>
#include <math.h>

#define S   129
#define SV  (S*S*S)
#define L   224
#define L2  (L*L)
#define LV  (L*L*L)
#define OFF 48           // L/2 - S/2
#define CABS 0.2f

// Scratch (allocation-free rule: __device__ globals)
// Transposed layout: up[column][z], column = y*L + x, z fastest.
__device__ float g_up0[LV];
__device__ float g_up1[LV];
// comb layout: [c][y][x][z], z fastest.
__device__ float g_comb[3 * SV];

struct Mat3 { float m[9]; };

// ---------- density sampler (129^3, zero padding) ----------

__device__ __forceinline__ float fetchS(const float* __restrict__ v, int z, int y, int x) {
    if ((unsigned)x < (unsigned)S && (unsigned)y < (unsigned)S && (unsigned)z < (unsigned)S)
        return __ldg(v + ((size_t)z * S + y) * S + x);
    return 0.f;
}

// Caller guarantees not fully-OOB; per-corner predicates handle the boundary.
__device__ __forceinline__ float triS(const float* __restrict__ v, float x, float y, float z) {
    float fx = floorf(x), fy = floorf(y), fz = floorf(z);
    int x0 = (int)fx, y0 = (int)fy, z0 = (int)fz;
    float wx = x - fx, wy = y - fy, wz = z - fz;
    float c000 = fetchS(v, z0,     y0,     x0);
    float c001 = fetchS(v, z0,     y0,     x0 + 1);
    float c010 = fetchS(v, z0,     y0 + 1, x0);
    float c011 = fetchS(v, z0,     y0 + 1, x0 + 1);
    float c100 = fetchS(v, z0 + 1, y0,     x0);
    float c101 = fetchS(v, z0 + 1, y0,     x0 + 1);
    float c110 = fetchS(v, z0 + 1, y0 + 1, x0);
    float c111 = fetchS(v, z0 + 1, y0 + 1, x0 + 1);
    float c00 = c000 + wx * (c001 - c000);
    float c01 = c010 + wx * (c011 - c010);
    float c10 = c100 + wx * (c101 - c100);
    float c11 = c110 + wx * (c111 - c110);
    float c0  = c00 + wy * (c01 - c00);
    float c1  = c10 + wy * (c11 - c10);
    return c0 + wz * (c1 - c0);
}

// ---------- transmittance sampler (224^3, transposed [y][x][z]) ----------

__device__ __forceinline__ float fetchLT(const float* __restrict__ v, int z, int y, int x) {
    if ((unsigned)x < (unsigned)L && (unsigned)y < (unsigned)L && (unsigned)z < (unsigned)L)
        return __ldg(v + ((size_t)y * L + x) * L + z);
    return 0.f;
}

__device__ __forceinline__ float triLT(const float* __restrict__ v, float x, float y, float z) {
    float fx = floorf(x), fy = floorf(y), fz = floorf(z);
    int x0 = (int)fx, y0 = (int)fy, z0 = (int)fz;
    float wx = x - fx, wy = y - fy, wz = z - fz;
    float c000 = fetchLT(v, z0,     y0,     x0);
    float c001 = fetchLT(v, z0,     y0,     x0 + 1);
    float c010 = fetchLT(v, z0,     y0 + 1, x0);
    float c011 = fetchLT(v, z0,     y0 + 1, x0 + 1);
    float c100 = fetchLT(v, z0 + 1, y0,     x0);
    float c101 = fetchLT(v, z0 + 1, y0,     x0 + 1);
    float c110 = fetchLT(v, z0 + 1, y0 + 1, x0);
    float c111 = fetchLT(v, z0 + 1, y0 + 1, x0 + 1);
    float c00 = c000 + wx * (c001 - c000);
    float c01 = c010 + wx * (c011 - c010);
    float c10 = c100 + wx * (c101 - c100);
    float c11 = c110 + wx * (c111 - c110);
    float c0  = c00 + wy * (c01 - c00);
    float c1  = c10 + wy * (c11 - c10);
    return c0 + wz * (c1 - c0);
}

// warp-wide suffix (reverse inclusive) scan: s_l = sum_{m>=l} v_m
__device__ __forceinline__ float warp_suffix_scan(float s, int lane) {
    #pragma unroll
    for (int off = 1; off < 32; off <<= 1) {
        float t = __shfl_down_sync(0xffffffffu, s, off);
        if (lane < 32 - off) s += t;
    }
    return s;
}

// ---------- kernel A: rotate + suffix-cumsum + exp, one WARP per (y,x) column ----------
// up_t[col][z] = exp(-c * sum_{z'>=z} rot(d)[z',col]) ; blockIdx.y = light
__global__ void __launch_bounds__(128) kA(const float* __restrict__ d, Mat3 R0, Mat3 R1) {
    int warp = threadIdx.x >> 5, lane = threadIdx.x & 31;
    int t = blockIdx.x * 4 + warp;               // column id, exact (12544*4 = L2)
    const Mat3 R = blockIdx.y ? R1 : R0;
    float* __restrict__ up = blockIdx.y ? g_up1 : g_up0;
    int x = t % L, y = t / L;
    float bx = -1.f + 2.f * (float)x / 223.f;
    float by = -1.f + 2.f * (float)y / 223.f;
    float A0 = 111.5f * (R.m[0] * bx + R.m[1] * by + 1.f - R.m[2]) - (float)OFF;
    float A1 = 111.5f * (R.m[3] * bx + R.m[4] * by + 1.f - R.m[5]) - (float)OFF;
    float A2 = 111.5f * (R.m[6] * bx + R.m[7] * by + 1.f - R.m[8]) - (float)OFF;
    float D0 = R.m[2], D1 = R.m[5], D2 = R.m[8];
    float carry = 0.f;
    float* __restrict__ col = up + (size_t)t * L;
    #pragma unroll
    for (int c = 0; c < 7; ++c) {
        int zb = 192 - 32 * c;                   // chunks high-z -> low-z
        float zf = (float)(zb + lane);
        float px = fmaf(zf, D0, A0);
        float py = fmaf(zf, D1, A1);
        float pz = fmaf(zf, D2, A2);
        bool inb = (px > -1.f) && (px < (float)S) &&
                   (py > -1.f) && (py < (float)S) &&
                   (pz > -1.f) && (pz < (float)S);
        unsigned b = __ballot_sync(0xffffffffu, inb);
        if (b == 0) {
            col[zb + lane] = __expf(-CABS * carry);   // no density in this chunk
        } else {
            float dv = inb ? triS(d, px, py, pz) : 0.f;
            float s = warp_suffix_scan(dv, lane);
            col[zb + lane] = __expf(-CABS * (carry + s));
            carry += __shfl_sync(0xffffffffu, s, 0);
        }
    }
}

// ---------- kernel B: back-rotate both lights -> 3-channel combined field ----------
// comb[c][y][x][z]; thread id v has z fastest for coalesced writes.
__global__ void __launch_bounds__(256) kB(Mat3 R0, Mat3 R1) {
    int v = blockIdx.x * 256 + threadIdx.x;
    if (v >= SV) return;
    int z = v % S;
    int x = (v / S) % S;
    int y = v / (S * S);
    float bx = -1.f + 2.f * (float)(x + OFF) / 223.f;
    float by = -1.f + 2.f * (float)(y + OFF) / 223.f;
    float bz = -1.f + 2.f * (float)(z + OFF) / 223.f;
    // back matrix = R^T: src_k = sum_c R[c,k]*b_c
    float s0 = triLT(g_up0,
        111.5f * (R0.m[0] * bx + R0.m[3] * by + R0.m[6] * bz + 1.f),
        111.5f * (R0.m[1] * bx + R0.m[4] * by + R0.m[7] * bz + 1.f),
        111.5f * (R0.m[2] * bx + R0.m[5] * by + R0.m[8] * bz + 1.f));
    float s1 = triLT(g_up1,
        111.5f * (R1.m[0] * bx + R1.m[3] * by + R1.m[6] * bz + 1.f),
        111.5f * (R1.m[1] * bx + R1.m[4] * by + R1.m[7] * bz + 1.f),
        111.5f * (R1.m[2] * bx + R1.m[5] * by + R1.m[8] * bz + 1.f));
    // rgb0 = (1, 69/255, 25/255), rgb1 = (227/255, 1, 66/255)
    g_comb[v]          = s0 * 1.0f           + s1 * (227.f / 255.f);
    g_comb[SV + v]     = s0 * (69.f / 255.f) + s1 * 1.0f;
    g_comb[2 * SV + v] = s0 * (25.f / 255.f) + s1 * (66.f / 255.f);
}

// ---------- kernel C: view-ray compositing, one WARP per pixel ----------
__global__ void __launch_bounds__(128) kC(const float* __restrict__ d, float* __restrict__ out) {
    int warp = threadIdx.x >> 5, lane = threadIdx.x & 31;
    int t = blockIdx.x * 4 + warp;               // pixel id
    if (t >= S * S) return;
    int x = t % S, y = t / S;
    const float* __restrict__ c0 = g_comb + ((size_t)y * S + x) * S;   // + z
    const float* __restrict__ c1 = c0 + SV;
    const float* __restrict__ c2 = c0 + 2 * SV;
    float carry = 0.f, a0 = 0.f, a1 = 0.f, a2 = 0.f;
    #pragma unroll
    for (int c = 0; c < 5; ++c) {
        int z = (97 - 32 * c) + lane;            // bases 97,65,33,1,-31 cover 0..128
        bool valid = z >= 0;
        float dv = valid ? __ldg(d + (size_t)z * S * S + t) : 0.f;
        float s = warp_suffix_scan(dv, lane);
        float tr = __expf(-CABS * (carry + s));
        float w = dv * tr;
        if (valid) {
            a0 = fmaf(w, __ldg(c0 + z), a0);
            a1 = fmaf(w, __ldg(c1 + z), a1);
            a2 = fmaf(w, __ldg(c2 + z), a2);
        }
        carry += __shfl_sync(0xffffffffu, s, 0);
    }
    #pragma unroll
    for (int off = 16; off; off >>= 1) {
        a0 += __shfl_xor_sync(0xffffffffu, a0, off);
        a1 += __shfl_xor_sync(0xffffffffu, a1, off);
        a2 += __shfl_xor_sync(0xffffffffu, a2, off);
    }
    if (lane == 0) {
        out[t]             = fminf(fmaxf(CABS * a0, 0.f), 1.f);
        out[S * S + t]     = fminf(fmaxf(CABS * a1, 0.f), 1.f);
        out[2 * S * S + t] = fminf(fmaxf(CABS * a2, 0.f), 1.f);
    }
}

// ---------- host ----------

static void light_matrix(double lx, double ly, double lz, Mat3* Rf) {
    double n = sqrt(lx * lx + ly * ly + lz * lz);
    double ldx = lx / n, ldy = ly / n, ldz = lz / n;
    double yw = -asin(ldx);
    if (ldz < 0) yw = -M_PI - yw;
    double p = asin(ldy);
    double cy = cos(yw), sy = sin(yw), cp = cos(p), sp = sin(p);
    // R = Ry @ Rp
    double R[9] = { cy,  sy * sp,  sy * cp,
                    0.0, cp,      -sp,
                   -sy,  cy * sp,  cy * cp };
    for (int i = 0; i < 9; i++) Rf->m[i] = (float)R[i];
}

extern "C" void kernel_launch(void* const* d_in, const int* in_sizes, int n_in,
                              void* d_out, int out_size) {
    const float* d = (const float*)d_in[0];
    float* out = (float*)d_out;

    Mat3 R0, R1;
    light_matrix(2.0, 1.0, 1.0, &R0);
    light_matrix(-1.0, 0.5, 0.0, &R1);

    dim3 gridA(L2 / 4, 2, 1);                    // warp per column, 4 warps/block
    kA<<<gridA, 128>>>(d, R0, R1);
    kB<<<(SV + 255) / 256, 256>>>(R0, R1);
    kC<<<(S * S + 3) / 4, 128>>>(d, out);
}

// round 5
// speedup vs baseline: 1.8002x; 1.0805x over previous
#include <cuda_runtime.h>
#include <math.h>

#define S    129
#define SS   (S*S)            // 16641
#define SV   (S*S*S)          // 2146689
#define P    131              // padded side (1-voxel zero border)
#define PP   (P*P)            // 17161
#define PV   (P*P*P)          // 2248091
#define L    224
#define LL2  (L*L)            // 50176
#define LV   (L*L*L)          // 11239424
#define OFF  48               // L/2 - S/2
#define CABS 0.2f

// Scratch (allocation-free rule: __device__ globals; zero-initialized at load).
// g_pd: density in a 131^3 buffer with a 1-voxel zero border on every face;
// the border is never written, so an unpredicated trilinear over it reproduces
// the reference's zero-padding corner masking exactly (coords are guaranteed
// in (-1,S) per axis by the caller, so shifted corner indices stay in [0,130]).
__device__ float g_pd[PV];
// Transmittance volumes, [y][x][z] layout. Back-rotation samples are provably
// interior (max |normalized src| <= 0.98), so no padding needed.
__device__ float g_upb[2][LV];

struct Mat3 { float m[9]; };

// ---------- unpredicated trilinear over padded density ----------
__device__ __forceinline__ float triS_fast(const float* __restrict__ pd,
                                           float x, float y, float z) {
    float fx = floorf(x), fy = floorf(y), fz = floorf(z);
    int ib = ((int)fz + 1) * PP + ((int)fy + 1) * P + ((int)fx + 1);
    float wx = x - fx, wy = y - fy, wz = z - fz;
    const float* p = pd + ib;
    float c000 = __ldg(p);
    float c001 = __ldg(p + 1);
    float c010 = __ldg(p + P);
    float c011 = __ldg(p + P + 1);
    float c100 = __ldg(p + PP);
    float c101 = __ldg(p + PP + 1);
    float c110 = __ldg(p + PP + P);
    float c111 = __ldg(p + PP + P + 1);
    float c00 = c000 + wx * (c001 - c000);
    float c01 = c010 + wx * (c011 - c010);
    float c10 = c100 + wx * (c101 - c100);
    float c11 = c110 + wx * (c111 - c110);
    float c0  = c00 + wy * (c01 - c00);
    float c1  = c10 + wy * (c11 - c10);
    return c0 + wz * (c1 - c0);
}

// ---------- unpredicated trilinear over up volume ([y][x][z]) ----------
__device__ __forceinline__ float triLT_fast(const float* __restrict__ v,
                                            float x, float y, float z) {
    float fx = floorf(x), fy = floorf(y), fz = floorf(z);
    int ib = ((int)fy * L + (int)fx) * L + (int)fz;
    float wx = x - fx, wy = y - fy, wz = z - fz;
    const float* p = v + ib;
    float c000 = __ldg(p);               // (z0,   y0,   x0)
    float c100 = __ldg(p + 1);           // (z0+1, y0,   x0)
    float c001 = __ldg(p + L);           // (z0,   y0,   x0+1)
    float c101 = __ldg(p + L + 1);
    float c010 = __ldg(p + LL2);         // (z0,   y0+1, x0)
    float c110 = __ldg(p + LL2 + 1);
    float c011 = __ldg(p + LL2 + L);
    float c111 = __ldg(p + LL2 + L + 1);
    float c00 = c000 + wx * (c001 - c000);
    float c01 = c010 + wx * (c011 - c010);
    float c10 = c100 + wx * (c101 - c100);
    float c11 = c110 + wx * (c111 - c110);
    float c0  = c00 + wy * (c01 - c00);
    float c1  = c10 + wy * (c11 - c10);
    return c0 + wz * (c1 - c0);
}

// warp-wide suffix (reverse inclusive) scan: s_l = sum_{m>=l} v_m
__device__ __forceinline__ float warp_suffix_scan(float s, int lane) {
    #pragma unroll
    for (int off = 1; off < 32; off <<= 1) {
        float t = __shfl_down_sync(0xffffffffu, s, off);
        if (lane < 32 - off) s += t;
    }
    return s;
}

// ---------- kernel P: copy density into bordered buffer ----------
__global__ void __launch_bounds__(256) kP(const float* __restrict__ d) {
    int i = blockIdx.x * 256 + threadIdx.x;
    if (i >= SV) return;
    int x = i % S, y = (i / S) % S, z = i / SS;
    g_pd[(z + 1) * PP + (y + 1) * P + (x + 1)] = __ldg(d + i);
}

// ---------- kernel A: rotate + suffix-cumsum + exp, one WARP per (y,x) column ----------
// up[col][z] = exp(-c * sum_{z'>=z} rot(d)[z',col]) ; blockIdx.y = light
__global__ void __launch_bounds__(128) kA(Mat3 R0, Mat3 R1) {
    int warp = threadIdx.x >> 5, lane = threadIdx.x & 31;
    int t = blockIdx.x * 4 + warp;               // column id, exact (12544*4 = L^2)
    const Mat3 R = blockIdx.y ? R1 : R0;
    float* __restrict__ up = g_upb[blockIdx.y];
    int x = t % L, y = t / L;
    float bx = -1.f + 2.f * (float)x / 223.f;
    float by = -1.f + 2.f * (float)y / 223.f;
    float A0 = 111.5f * (R.m[0] * bx + R.m[1] * by + 1.f - R.m[2]) - (float)OFF;
    float A1 = 111.5f * (R.m[3] * bx + R.m[4] * by + 1.f - R.m[5]) - (float)OFF;
    float A2 = 111.5f * (R.m[6] * bx + R.m[7] * by + 1.f - R.m[8]) - (float)OFF;
    float D0 = R.m[2], D1 = R.m[5], D2 = R.m[8];
    float carry = 0.f;
    float* __restrict__ col = up + (size_t)t * L;
    #pragma unroll
    for (int c = 0; c < 7; ++c) {
        int zb = 192 - 32 * c;                   // chunks high-z -> low-z
        float zf = (float)(zb + lane);
        float px = fmaf(zf, D0, A0);
        float py = fmaf(zf, D1, A1);
        float pz = fmaf(zf, D2, A2);
        bool inb = (px > -1.f) && (px < (float)S) &&
                   (py > -1.f) && (py < (float)S) &&
                   (pz > -1.f) && (pz < (float)S);
        unsigned b = __ballot_sync(0xffffffffu, inb);
        if (b == 0) {
            col[zb + lane] = __expf(-CABS * carry);   // no density in this chunk
        } else {
            float dv = inb ? triS_fast(g_pd, px, py, pz) : 0.f;
            float s = warp_suffix_scan(dv, lane);
            col[zb + lane] = __expf(-CABS * (carry + s));
            carry += __shfl_sync(0xffffffffu, s, 0);
        }
    }
}

// ---------- kernel BC: back-rotate both lights + composite, one WARP per pixel ----------
__global__ void __launch_bounds__(128) kBC(const float* __restrict__ d,
                                           Mat3 R0, Mat3 R1,
                                           float* __restrict__ out) {
    int warp = threadIdx.x >> 5, lane = threadIdx.x & 31;
    int t = blockIdx.x * 4 + warp;               // pixel id
    if (t >= SS) return;
    int x = t % S, y = t / S;
    const float* __restrict__ up0 = g_upb[0];
    const float* __restrict__ up1 = g_upb[1];
    float bx = -1.f + 2.f * (float)(x + OFF) / 223.f;
    float by = -1.f + 2.f * (float)(y + OFF) / 223.f;
    // back matrix = R^T: src_k = R[0,k]bx + R[1,k]by + R[2,k]bz, affine in z with
    // unit slope coefficient R[2,k] (111.5 * 2/223 == 1 exactly).
    float bz0 = -1.f + 2.f * (float)OFF / 223.f;
    float B00 = 111.5f * (R0.m[0] * bx + R0.m[3] * by + R0.m[6] * bz0 + 1.f);
    float B01 = 111.5f * (R0.m[1] * bx + R0.m[4] * by + R0.m[7] * bz0 + 1.f);
    float B02 = 111.5f * (R0.m[2] * bx + R0.m[5] * by + R0.m[8] * bz0 + 1.f);
    float B10 = 111.5f * (R1.m[0] * bx + R1.m[3] * by + R1.m[6] * bz0 + 1.f);
    float B11 = 111.5f * (R1.m[1] * bx + R1.m[4] * by + R1.m[7] * bz0 + 1.f);
    float B12 = 111.5f * (R1.m[2] * bx + R1.m[5] * by + R1.m[8] * bz0 + 1.f);
    float carry = 0.f, a0 = 0.f, a1 = 0.f, a2 = 0.f;
    const float c227 = 227.f / 255.f, c69 = 69.f / 255.f, c25 = 25.f / 255.f, c66 = 66.f / 255.f;
    #pragma unroll
    for (int c = 0; c < 5; ++c) {
        int z = (97 - 32 * c) + lane;            // bases 97,65,33,1,-31 cover 0..128
        bool valid = z >= 0;
        float dv = 0.f, comb0 = 0.f, comb1 = 0.f, comb2 = 0.f;
        if (valid) {
            float zf = (float)z;
            dv = __ldg(d + (size_t)z * SS + t);
            float s0 = triLT_fast(up0, fmaf(zf, R0.m[6], B00),
                                       fmaf(zf, R0.m[7], B01),
                                       fmaf(zf, R0.m[8], B02));
            float s1 = triLT_fast(up1, fmaf(zf, R1.m[6], B10),
                                       fmaf(zf, R1.m[7], B11),
                                       fmaf(zf, R1.m[8], B12));
            comb0 = s0        + s1 * c227;
            comb1 = s0 * c69  + s1;
            comb2 = s0 * c25  + s1 * c66;
        }
        float s = warp_suffix_scan(dv, lane);
        float tr = __expf(-CABS * (carry + s));
        float w = dv * tr;
        a0 = fmaf(w, comb0, a0);
        a1 = fmaf(w, comb1, a1);
        a2 = fmaf(w, comb2, a2);
        carry += __shfl_sync(0xffffffffu, s, 0);
    }
    #pragma unroll
    for (int off = 16; off; off >>= 1) {
        a0 += __shfl_xor_sync(0xffffffffu, a0, off);
        a1 += __shfl_xor_sync(0xffffffffu, a1, off);
        a2 += __shfl_xor_sync(0xffffffffu, a2, off);
    }
    if (lane == 0) {
        out[t]          = fminf(fmaxf(CABS * a0, 0.f), 1.f);
        out[SS + t]     = fminf(fmaxf(CABS * a1, 0.f), 1.f);
        out[2 * SS + t] = fminf(fmaxf(CABS * a2, 0.f), 1.f);
    }
}

// ---------- host ----------

static void light_matrix(double lx, double ly, double lz, Mat3* Rf) {
    double n = sqrt(lx * lx + ly * ly + lz * lz);
    double ldx = lx / n, ldy = ly / n, ldz = lz / n;
    double yw = -asin(ldx);
    if (ldz < 0) yw = -M_PI - yw;
    double p = asin(ldy);
    double cy = cos(yw), sy = sin(yw), cp = cos(p), sp = sin(p);
    // R = Ry @ Rp
    double R[9] = { cy,  sy * sp,  sy * cp,
                    0.0, cp,      -sp,
                   -sy,  cy * sp,  cy * cp };
    for (int i = 0; i < 9; i++) Rf->m[i] = (float)R[i];
}

extern "C" void kernel_launch(void* const* d_in, const int* in_sizes, int n_in,
                              void* d_out, int out_size) {
    const float* d = (const float*)d_in[0];
    float* out = (float*)d_out;

    Mat3 R0, R1;
    light_matrix(2.0, 1.0, 1.0, &R0);
    light_matrix(-1.0, 0.5, 0.0, &R1);

    kP<<<(SV + 255) / 256, 256>>>(d);
    dim3 gridA(LL2 / 4, 2, 1);                   // warp per column, 4 warps/block
    kA<<<gridA, 128>>>(R0, R1);
    kBC<<<(SS + 3) / 4, 128>>>(d, R0, R1, out);
}